// round 16
// baseline (speedup 1.0000x reference)
#include <cuda_runtime.h>
#include <cuda_bf16.h>
#include <cstdint>
#include <math.h>

#define T_ 256
#define B_ 128
#define H_ 1024
#define H2 512                    /* H/2 packed u32 pairs */
#define L_ 4
#define TB_ 32768
#define BH_ 131072
#define TBH_ 33554432
#define LHH2 (L_ * H_ * H2)       /* 2097152 */

// ---------------------------------------------------------------------------
// Device globals (allocation-free scratch)
// ---------------------------------------------------------------------------
__device__ float g_P[TBH_];
__device__ uint32_t g_xhi0[TB_ * H2];
__device__ uint32_t g_xlo0[TB_ * H2];
__device__ uint32_t g_xhi1[TB_ * H2];
__device__ uint32_t g_xlo1[TB_ * H2];
__device__ uint32_t g_uihi[LHH2], g_uilo[LHH2];
__device__ uint32_t g_whhi[LHH2], g_whlo[LHH2];
__device__ uint32_t g_hxhi[L_ * B_ * H2], g_hxlo[L_ * B_ * H2];
// Per-layer, per-(m-group, n-tile) step-completion flags. Cleared every call.
__device__ unsigned int g_flagL[L_][4][32];

// ---------------------------------------------------------------------------
// Helpers
// ---------------------------------------------------------------------------
__device__ __forceinline__ uint32_t smem_u32(const void* p) {
    uint32_t a;
    asm("{ .reg .u64 t; cvta.to.shared.u64 t, %1; cvt.u32.u64 %0, t; }" : "=r"(a) : "l"(p));
    return a;
}
__device__ __forceinline__ void splitpack(float x0, float x1, uint32_t& hi, uint32_t& lo) {
    __nv_bfloat16 h0 = __float2bfloat16(x0);
    __nv_bfloat16 h1 = __float2bfloat16(x1);
    __nv_bfloat16 l0 = __float2bfloat16(x0 - __bfloat162float(h0));
    __nv_bfloat16 l1 = __float2bfloat16(x1 - __bfloat162float(h1));
    hi = (uint32_t)__bfloat16_as_ushort(h0) | ((uint32_t)__bfloat16_as_ushort(h1) << 16);
    lo = (uint32_t)__bfloat16_as_ushort(l0) | ((uint32_t)__bfloat16_as_ushort(l1) << 16);
}
__device__ __forceinline__ void mma16(float* d, const uint32_t* a, uint32_t b0, uint32_t b1) {
    asm volatile("mma.sync.aligned.m16n8k16.row.col.f32.bf16.bf16.f32 "
                 "{%0,%1,%2,%3}, {%4,%5,%6,%7}, {%8,%9}, {%0,%1,%2,%3};"
                 : "+f"(d[0]), "+f"(d[1]), "+f"(d[2]), "+f"(d[3])
                 : "r"(a[0]), "r"(a[1]), "r"(a[2]), "r"(a[3]), "r"(b0), "r"(b1));
}
#define LDSM4(r, addr) \
    asm volatile("ldmatrix.sync.aligned.m8n8.x4.shared.b16 {%0,%1,%2,%3}, [%4];" \
                 : "=r"((r)[0]), "=r"((r)[1]), "=r"((r)[2]), "=r"((r)[3]) : "r"(addr))
#define CP_ASYNC16(dst_u32, src_ptr) \
    asm volatile("cp.async.cg.shared.global [%0], [%1], 16;" \
                 :: "r"(dst_u32), "l"(src_ptr) : "memory")
#define CP_COMMIT() asm volatile("cp.async.commit_group;" ::: "memory")
#define CP_WAIT2()  asm volatile("cp.async.wait_group 2;" ::: "memory")
#define CP_WAIT1()  asm volatile("cp.async.wait_group 1;" ::: "memory")
#define CP_WAIT0()  asm volatile("cp.async.wait_group 0;" ::: "memory")
#define BAR_SYNC(id, cnt) \
    asm volatile("bar.sync %0, %1;" :: "r"(id), "r"(cnt) : "memory")

__device__ __forceinline__ void red_add_release(unsigned* p) {
    asm volatile("red.add.release.gpu.global.u32 [%0], 1;" :: "l"(p) : "memory");
}
__device__ __forceinline__ unsigned ld_acquire(const unsigned* p) {
    unsigned v;
    asm volatile("ld.acquire.gpu.global.u32 %0, [%1];" : "=r"(v) : "l"(p) : "memory");
    return v;
}
__device__ __forceinline__ float fast_tanh(float x) {
    const float e = __expf(2.0f * x);
    return 1.0f - __fdividef(2.0f, e + 1.0f);
}

// ---------------------------------------------------------------------------
// One-time splits (+ flag clear)
// ---------------------------------------------------------------------------
__global__ __launch_bounds__(256)
void split_w_kernel(const float* __restrict__ Wih, const float* __restrict__ Whh)
{
    const size_t i = (size_t)blockIdx.x * 256 + threadIdx.x;
    uint32_t hi, lo;
    splitpack(Wih[2 * i], Wih[2 * i + 1], hi, lo);
    g_uihi[i] = hi; g_uilo[i] = lo;
    splitpack(Whh[2 * i], Whh[2 * i + 1], hi, lo);
    g_whhi[i] = hi; g_whlo[i] = lo;
}
__global__ __launch_bounds__(256)
void split_x_kernel(const float* __restrict__ X)
{
    const size_t i = (size_t)blockIdx.x * 256 + threadIdx.x;
    uint32_t hi, lo;
    splitpack(X[2 * i], X[2 * i + 1], hi, lo);
    g_xhi0[i] = hi; g_xlo0[i] = lo;
}
__global__ __launch_bounds__(256)
void split_hx_kernel(const float* __restrict__ hx)
{
    const size_t i = (size_t)blockIdx.x * 256 + threadIdx.x;
    uint32_t hi, lo;
    splitpack(hx[2 * i], hx[2 * i + 1], hi, lo);
    g_hxhi[i] = hi; g_hxlo[i] = lo;
    // Block 0 also clears all step flags (L_*4*32 = 512 words).
    if (blockIdx.x == 0) {
        unsigned* f = &g_flagL[0][0][0];
        f[threadIdx.x] = 0u;
        f[threadIdx.x + 256] = 0u;
    }
}

// ---------------------------------------------------------------------------
// Input projection (unchanged): P = X @ W^T + bi + bh.
// ---------------------------------------------------------------------------
#define P_STR 20
#define P_SAHI 0
#define P_SALO 2560
#define P_SBHI 5120
#define P_SBLO 6400
#define P_SMEM_BYTES (7680u * 4u)

__global__ __launch_bounds__(256, 2)
void proj_kernel(const uint32_t* __restrict__ Xhi, const uint32_t* __restrict__ Xlo,
                 const uint32_t* __restrict__ Whi_, const uint32_t* __restrict__ Wlo_,
                 const float* __restrict__ bi, const float* __restrict__ bhh,
                 float* __restrict__ P)
{
    extern __shared__ uint32_t sm[];
    const uint32_t smb = smem_u32(sm);
    const int tid = threadIdx.x, wid = tid >> 5, lane = tid & 31;
    const int grp = lane >> 2, qid = lane & 3;
    const int m0 = blockIdx.y * 128, n0 = blockIdx.x * 64;
    const int wm = (wid >> 1) * 32, wn = (wid & 1) * 32;

    const int arow_f = (lane & 7) + ((lane >> 3) & 1) * 8;
    const uint32_t akh = (lane >> 4) * 4;
    const uint32_t aoff0 = (uint32_t)(wm + arow_f) * P_STR + akh;
    const uint32_t aoff1 = (uint32_t)(wm + 16 + arow_f) * P_STR + akh;
    const int mB = lane >> 3;
    const int brow_f = (mB >> 1) * 8 + (lane & 7);
    const uint32_t bkh = (uint32_t)(mB & 1) * 4;
    const uint32_t boff0 = (uint32_t)(wn + brow_f) * P_STR + bkh;
    const uint32_t boff1 = (uint32_t)(wn + 16 + brow_f) * P_STR + bkh;

    const int arow = tid >> 1, acg = (tid & 1) * 8;
    const int brow = tid >> 2, bcg = (tid & 3) * 4;

    const uint32_t* Ah = Xhi  + (size_t)(m0 + arow) * H2 + acg;
    const uint32_t* Al = Xlo  + (size_t)(m0 + arow) * H2 + acg;
    const uint32_t* Bh = Whi_ + (size_t)(n0 + brow) * H2 + bcg;
    const uint32_t* Bl = Wlo_ + (size_t)(n0 + brow) * H2 + bcg;

    float acc[2][4][4];
#pragma unroll
    for (int mt = 0; mt < 2; mt++)
#pragma unroll
        for (int nt = 0; nt < 4; nt++)
#pragma unroll
            for (int i = 0; i < 4; i++) acc[mt][nt][i] = 0.0f;

    uint4 rah0 = *(const uint4*)Ah, rah1 = *(const uint4*)(Ah + 4);
    uint4 ral0 = *(const uint4*)Al, ral1 = *(const uint4*)(Al + 4);
    uint4 rbh  = *(const uint4*)Bh, rbl  = *(const uint4*)Bl;

    for (int kb2 = 0; kb2 < H2; kb2 += 16) {
        __syncthreads();
        *(uint4*)&sm[P_SAHI + arow * P_STR + acg]     = rah0;
        *(uint4*)&sm[P_SAHI + arow * P_STR + acg + 4] = rah1;
        *(uint4*)&sm[P_SALO + arow * P_STR + acg]     = ral0;
        *(uint4*)&sm[P_SALO + arow * P_STR + acg + 4] = ral1;
        *(uint4*)&sm[P_SBHI + brow * P_STR + bcg]     = rbh;
        *(uint4*)&sm[P_SBLO + brow * P_STR + bcg]     = rbl;
        __syncthreads();
        if (kb2 + 16 < H2) {
            rah0 = *(const uint4*)(Ah + kb2 + 16); rah1 = *(const uint4*)(Ah + kb2 + 20);
            ral0 = *(const uint4*)(Al + kb2 + 16); ral1 = *(const uint4*)(Al + kb2 + 20);
            rbh  = *(const uint4*)(Bh + kb2 + 16); rbl  = *(const uint4*)(Bl + kb2 + 16);
        }
#pragma unroll
        for (int kk = 0; kk < 2; kk++) {
            const uint32_t kb8 = kk * 8;
            uint32_t ah0[4], ah1[4], al0[4], al1[4];
            uint32_t bh01[4], bh23[4], bl01[4], bl23[4];
            LDSM4(ah0, smb + 4 * (P_SAHI + aoff0 + kb8));
            LDSM4(ah1, smb + 4 * (P_SAHI + aoff1 + kb8));
            LDSM4(al0, smb + 4 * (P_SALO + aoff0 + kb8));
            LDSM4(al1, smb + 4 * (P_SALO + aoff1 + kb8));
            LDSM4(bh01, smb + 4 * (P_SBHI + boff0 + kb8));
            LDSM4(bh23, smb + 4 * (P_SBHI + boff1 + kb8));
            LDSM4(bl01, smb + 4 * (P_SBLO + boff0 + kb8));
            LDSM4(bl23, smb + 4 * (P_SBLO + boff1 + kb8));
#pragma unroll
            for (int nt = 0; nt < 4; nt++) {
                const uint32_t* bhp = (nt < 2) ? bh01 : bh23;
                const uint32_t* blp = (nt < 2) ? bl01 : bl23;
                const int o = (nt & 1) * 2;
                mma16(acc[0][nt], ah0, bhp[o], bhp[o + 1]);
                mma16(acc[1][nt], ah1, bhp[o], bhp[o + 1]);
                mma16(acc[0][nt], ah0, blp[o], blp[o + 1]);
                mma16(acc[1][nt], ah1, blp[o], blp[o + 1]);
                mma16(acc[0][nt], al0, bhp[o], bhp[o + 1]);
                mma16(acc[1][nt], al1, bhp[o], bhp[o + 1]);
            }
        }
    }

#pragma unroll
    for (int mt = 0; mt < 2; mt++) {
#pragma unroll
        for (int nt = 0; nt < 4; nt++) {
            const int col = n0 + wn + nt * 8 + 2 * qid;
            const float bx = bi[col] + bhh[col];
            const float by = bi[col + 1] + bhh[col + 1];
            const int r0 = m0 + wm + mt * 16 + grp;
            float2 v0 = { acc[mt][nt][0] + bx, acc[mt][nt][1] + by };
            float2 v1 = { acc[mt][nt][2] + bx, acc[mt][nt][3] + by };
            *(float2*)&P[(size_t)r0 * H_ + col] = v0;
            *(float2*)&P[(size_t)(r0 + 8) * H_ + col] = v1;
        }
    }
}

// ---------------------------------------------------------------------------
// Persistent recurrence with producer-flag wavefront sync (no global barrier).
// Grid (32 n-tiles, 4 m-groups) = 128 CTAs, 256 thr (8 warps, 2 K-groups).
// Chunk c of group g depends on exactly 2 producer CTAs (n-tiles g*16+2c,+1)
// of the same m-group; cp.async.cg gated per-chunk on their step flags.
// ---------------------------------------------------------------------------
#define R_WSTR 516
#define R_ASTR 36
#define R_WHI 0
#define R_WLO 16512
#define R_ABUF 33024
#define R_ABUFSZ 2304            /* per stage: hi 1152 + lo 1152 */
#define R_RED (R_ABUF + 8 * R_ABUFSZ)       /* 51456; double-buffered 2x1024 */
#define R_SMEM_U32 (R_RED + 2048)
#define R_SMEM_BYTES (R_SMEM_U32 * 4u)      /* 214016 B */

__global__ __launch_bounds__(256, 1)
void recur_kernel(const uint32_t* __restrict__ hxhi, const uint32_t* __restrict__ hxlo,
                  const uint32_t* __restrict__ Whi_, const uint32_t* __restrict__ Wlo_,
                  const float* __restrict__ P,
                  uint32_t* __restrict__ pohi, uint32_t* __restrict__ polo,
                  float* __restrict__ Yout,
                  float* __restrict__ hn,
                  unsigned int* __restrict__ flg)     // [4][32] this layer
{
    extern __shared__ uint32_t sm[];
    const uint32_t smb = smem_u32(sm);

    const int tid = threadIdx.x, wid = tid >> 5, lane = tid & 31;
    const int grp = lane >> 2, qid = lane & 3;
    const int n0 = blockIdx.x * 32, mg = blockIdx.y, m0 = mg * 32;
    const int g = wid >> 2;
    const int wq = wid & 3;
    const int wm = (wq >> 1) * 16, wn = (wq & 1) * 16;
    const int gbase = g * 256;

    unsigned int* myflags = flg + mg * 32;       // flags of this m-group

    const uint32_t aoff = (uint32_t)(wm + (lane & 7) + ((lane >> 3) & 1) * 8) * R_ASTR
                        + (lane >> 4) * 4;
    const int mB = lane >> 3;
    const uint32_t boff = (uint32_t)(wn + (mB >> 1) * 8 + (lane & 7)) * R_WSTR
                        + (uint32_t)(mB & 1) * 4;

    // Stage W stripe.
    for (int idx = tid * 4; idx < 32 * H2; idx += 256 * 4) {
        const int r = idx >> 9, c = idx & (H2 - 1);
        *(uint4*)&sm[R_WHI + r * R_WSTR + c] = *(const uint4*)&Whi_[(size_t)(n0 + r) * H2 + c];
        *(uint4*)&sm[R_WLO + r * R_WSTR + c] = *(const uint4*)&Wlo_[(size_t)(n0 + r) * H2 + c];
    }
    __syncthreads();

    const int ltid = tid & 127;
    const int lrow = ltid >> 2, lcg = (ltid & 3) * 8;
    const uint32_t dst_hi = (uint32_t)(R_ABUF + g * 4 * R_ABUFSZ) + (uint32_t)lrow * R_ASTR + lcg;
    const uint32_t dst_lo = dst_hi + 1152;

    // P prefetch for t=0 (group 0 only).
    float2 pre[2][2];
    if (g == 0) {
#pragma unroll
        for (int nt = 0; nt < 2; nt++) {
            const int col = n0 + wn + nt * 8 + 2 * qid;
            const int r0 = m0 + wm + grp;
            pre[nt][0] = *(const float2*)&P[(size_t)r0 * H_ + col];
            pre[nt][1] = *(const float2*)&P[(size_t)(r0 + 8) * H_ + col];
        }
    }

    for (int t = 0; t < T_; t++) {
        const uint32_t* Ahp = t ? (pohi + (size_t)(t - 1) * (B_ * H2)) : hxhi;
        const uint32_t* Alp = t ? (polo + (size_t)(t - 1) * (B_ * H2)) : hxlo;
        const uint32_t* Ah = Ahp + (size_t)(m0 + lrow) * H2 + gbase + lcg;
        const uint32_t* Al = Alp + (size_t)(m0 + lrow) * H2 + gbase + lcg;
        const unsigned int target = (unsigned)t;   // h_{t-1} ready when flag >= t

        // Gate chunks 0..2 on their 6 producers, then issue.
        if (t) {
            if (lane < 6) {
                const unsigned int* f = &myflags[g * 16 + lane];
                while (ld_acquire(f) < target) __nanosleep(32);
            }
            __syncwarp();
        }
#pragma unroll
        for (int s = 0; s < 3; s++) {
            const uint32_t d  = 4 * (dst_hi + (uint32_t)s * R_ABUFSZ);
            const uint32_t dl = 4 * (dst_lo + (uint32_t)s * R_ABUFSZ);
            CP_ASYNC16(smb + d,       Ah + s * 32);
            CP_ASYNC16(smb + d + 16,  Ah + s * 32 + 4);
            CP_ASYNC16(smb + dl,      Al + s * 32);
            CP_ASYNC16(smb + dl + 16, Al + s * 32 + 4);
            CP_COMMIT();
        }

        float a00[4] = {0,0,0,0}, a01[4] = {0,0,0,0}, a02[4] = {0,0,0,0};
        float a10[4] = {0,0,0,0}, a11[4] = {0,0,0,0}, a12[4] = {0,0,0,0};

#pragma unroll
        for (int c = 0; c < 8; c++) {
            if (c <= 5) { CP_WAIT2(); } else if (c == 6) { CP_WAIT1(); } else { CP_WAIT0(); }
            BAR_SYNC(1 + g, 128);

            const uint32_t abase = smb + 4 * (R_ABUF + (g * 4 + (c & 3)) * R_ABUFSZ + aoff);
            const uint32_t kcb = gbase + c * 32;
#pragma unroll
            for (int kk = 0; kk < 4; kk++) {
                const uint32_t kb8 = kk * 8;
                uint32_t ah[4], al[4], bh[4], bl[4];
                LDSM4(ah, abase + 4 * kb8);
                LDSM4(al, abase + 4 * (1152 + kb8));
                LDSM4(bh, smb + 4 * (R_WHI + boff + kcb + kb8));
                LDSM4(bl, smb + 4 * (R_WLO + boff + kcb + kb8));
                mma16(a00, ah, bh[0], bh[1]);
                mma16(a10, ah, bh[2], bh[3]);
                mma16(a01, ah, bl[0], bl[1]);
                mma16(a11, ah, bl[2], bl[3]);
                mma16(a02, al, bh[0], bh[1]);
                mma16(a12, al, bh[2], bh[3]);
            }
            if (c < 5) {
                // Gate chunk c+3 on its 2 producers, then issue.
                if (t) {
                    if (lane < 2) {
                        const unsigned int* f = &myflags[g * 16 + 2 * (c + 3) + lane];
                        while (ld_acquire(f) < target) __nanosleep(32);
                    }
                    __syncwarp();
                }
                const int s = (c + 3) & 3;
                const uint32_t d  = 4 * (dst_hi + (uint32_t)s * R_ABUFSZ);
                const uint32_t dl = 4 * (dst_lo + (uint32_t)s * R_ABUFSZ);
                CP_ASYNC16(smb + d,       Ah + (c + 3) * 32);
                CP_ASYNC16(smb + d + 16,  Ah + (c + 3) * 32 + 4);
                CP_ASYNC16(smb + dl,      Al + (c + 3) * 32);
                CP_ASYNC16(smb + dl + 16, Al + (c + 3) * 32 + 4);
                CP_COMMIT();
            }
        }

        // Group 1 publishes partials (double-buffered); one CTA-wide sync.
        float* redw = (float*)&sm[R_RED + (t & 1) * 1024];
        if (g == 1) {
            const int base = (wq * 32 + lane) * 8;
#pragma unroll
            for (int i = 0; i < 4; i++) {
                redw[base + i]     = a00[i] + a01[i] + a02[i];
                redw[base + 4 + i] = a10[i] + a11[i] + a12[i];
            }
        }
        __syncthreads();

        if (g == 0) {
            const float* red = (const float*)redw;
            const int base = (wq * 32 + lane) * 8;
            const size_t pb = (size_t)t * (B_ * H2);
            const size_t tb = (size_t)t * BH_;
#pragma unroll
            for (int nt = 0; nt < 2; nt++) {
                float ac[4];
                if (nt == 0) {
#pragma unroll
                    for (int i = 0; i < 4; i++)
                        ac[i] = a00[i] + a01[i] + a02[i] + red[base + i];
                } else {
#pragma unroll
                    for (int i = 0; i < 4; i++)
                        ac[i] = a10[i] + a11[i] + a12[i] + red[base + 4 + i];
                }
                const int col = n0 + wn + nt * 8 + 2 * qid;
                const int r0 = m0 + wm + grp;
                const float v00 = fast_tanh(ac[0] + pre[nt][0].x);
                const float v01 = fast_tanh(ac[1] + pre[nt][0].y);
                const float v10 = fast_tanh(ac[2] + pre[nt][1].x);
                const float v11 = fast_tanh(ac[3] + pre[nt][1].y);
                uint32_t hi0, lo0, hi1, lo1;
                splitpack(v00, v01, hi0, lo0);
                splitpack(v10, v11, hi1, lo1);
                pohi[pb + (size_t)r0 * H2 + (col >> 1)] = hi0;
                polo[pb + (size_t)r0 * H2 + (col >> 1)] = lo0;
                pohi[pb + (size_t)(r0 + 8) * H2 + (col >> 1)] = hi1;
                polo[pb + (size_t)(r0 + 8) * H2 + (col >> 1)] = lo1;
                if (Yout) {
                    float2 a = { v00, v01 }, b = { v10, v11 };
                    *(float2*)&Yout[tb + (size_t)r0 * H_ + col] = a;
                    *(float2*)&Yout[tb + (size_t)(r0 + 8) * H_ + col] = b;
                }
                if (t == T_ - 1) {
                    float2 a = { v00, v01 }, b = { v10, v11 };
                    *(float2*)&hn[(size_t)r0 * H_ + col] = a;
                    *(float2*)&hn[(size_t)(r0 + 8) * H_ + col] = b;
                }
            }
            // Publish: h_t of this CTA is visible -> flag = t+1.
            BAR_SYNC(1, 128);                      // group-0 stores complete
            if (tid == 0) {
                __threadfence();
                red_add_release(&myflags[blockIdx.x]);
            }
            // Prefetch P for step t+1 (hidden behind next k-loop).
            if (t + 1 < T_) {
                const size_t tb1 = (size_t)(t + 1) * BH_;
#pragma unroll
                for (int nt = 0; nt < 2; nt++) {
                    const int col = n0 + wn + nt * 8 + 2 * qid;
                    const int r0 = m0 + wm + grp;
                    pre[nt][0] = *(const float2*)&P[tb1 + (size_t)r0 * H_ + col];
                    pre[nt][1] = *(const float2*)&P[tb1 + (size_t)(r0 + 8) * H_ + col];
                }
            }
        }
    }
}

// ---------------------------------------------------------------------------
extern "C" void kernel_launch(void* const* d_in, const int* in_sizes, int n_in,
                              void* d_out, int out_size)
{
    const float* inputs = (const float*)d_in[0];
    const float* hxs    = (const float*)d_in[1];
    const float* W_ih   = (const float*)d_in[2];
    const float* b_ih   = (const float*)d_in[3];
    const float* W_hh   = (const float*)d_in[4];
    const float* b_hh   = (const float*)d_in[5];
    float* out = (float*)d_out;

    float* P;
    uint32_t *xhi0, *xlo0, *xhi1, *xlo1, *uihi, *uilo, *whhi, *whlo, *hxhi, *hxlo;
    unsigned int* flg;
    cudaGetSymbolAddress((void**)&P, g_P);
    cudaGetSymbolAddress((void**)&xhi0, g_xhi0);
    cudaGetSymbolAddress((void**)&xlo0, g_xlo0);
    cudaGetSymbolAddress((void**)&xhi1, g_xhi1);
    cudaGetSymbolAddress((void**)&xlo1, g_xlo1);
    cudaGetSymbolAddress((void**)&uihi, g_uihi);
    cudaGetSymbolAddress((void**)&uilo, g_uilo);
    cudaGetSymbolAddress((void**)&whhi, g_whhi);
    cudaGetSymbolAddress((void**)&whlo, g_whlo);
    cudaGetSymbolAddress((void**)&hxhi, g_hxhi);
    cudaGetSymbolAddress((void**)&hxlo, g_hxlo);
    cudaGetSymbolAddress((void**)&flg, g_flagL);

    cudaFuncSetAttribute(proj_kernel,  cudaFuncAttributeMaxDynamicSharedMemorySize, P_SMEM_BYTES);
    cudaFuncSetAttribute(recur_kernel, cudaFuncAttributeMaxDynamicSharedMemorySize, R_SMEM_BYTES);

    split_w_kernel<<<LHH2 / 256, 256>>>(W_ih, W_hh);
    split_x_kernel<<<(TB_ * H2) / 256, 256>>>(inputs);
    split_hx_kernel<<<(L_ * B_ * H2) / 256, 256>>>(hxs);   // also clears flags

    uint32_t* xin_hi[2] = { xhi0, xhi1 };
    uint32_t* xin_lo[2] = { xlo0, xlo1 };

    const dim3 proj_grid(H_ / 64, TB_ / 128);   // (16, 256)
    const dim3 rec_grid(H_ / 32, B_ / 32);      // (32, 4) = 128 CTAs

    for (int l = 0; l < L_; l++) {
        const int pin = l & 1, pout = pin ^ 1;
        const size_t wo = (size_t)l * H_ * H2;

        proj_kernel<<<proj_grid, 256, P_SMEM_BYTES>>>(
            xin_hi[pin], xin_lo[pin], uihi + wo, uilo + wo,
            b_ih + (size_t)l * H_, b_hh + (size_t)l * H_, P);

        recur_kernel<<<rec_grid, 256, R_SMEM_BYTES>>>(
            hxhi + (size_t)l * (B_ * H2), hxlo + (size_t)l * (B_ * H2),
            whhi + wo, whlo + wo, P,
            xin_hi[pout], xin_lo[pout],
            (l == L_ - 1) ? out : nullptr,
            out + (size_t)TBH_ + (size_t)l * BH_,
            flg + (size_t)l * 128);
    }
}